// round 1
// baseline (speedup 1.0000x reference)
#include <cuda_runtime.h>
#include <math.h>

#define NNODES 50000
#define NEDGES 800000
#define SEQLEN 32
#define EMBD   128
#define INFEAT 256
#define NHID   256
#define NCLS   40

// ---------------- scratch (device globals; no allocation allowed) ------------
__device__ int   g_deg_out[NNODES];
__device__ int   g_deg_in[NNODES];
__device__ float g_norm_s[NNODES];
__device__ float g_norm_d[NNODES];
__device__ int   g_row_ptr[NNODES + 1];
__device__ int   g_cursor[NNODES];
__device__ int   g_chunk_off[1024];
__device__ int   g_csr_src[NEDGES];
__device__ float g_h[(size_t)NNODES * INFEAT];     // pooled embeddings [N,256]
__device__ float g_hws1[(size_t)NNODES * NHID];    // (h@W1)*norm_s
__device__ float g_out1[(size_t)NNODES * NHID];    // relu(agg*norm_d + b1)
__device__ float g_hws2[(size_t)NNODES * NCLS];    // (out1@W2)*norm_s

// ---------------- degree + norm ----------------------------------------------
__global__ void zero_degs_kernel() {
    int i = blockIdx.x * blockDim.x + threadIdx.x;
    if (i < NNODES) { g_deg_out[i] = 0; g_deg_in[i] = 0; }
}

__global__ void degree_kernel(const int* __restrict__ src, const int* __restrict__ dst) {
    int e = blockIdx.x * blockDim.x + threadIdx.x;
    if (e < NEDGES) {
        atomicAdd(&g_deg_out[src[e]], 1);
        atomicAdd(&g_deg_in[dst[e]], 1);
    }
}

__global__ void norm_kernel() {
    int v = blockIdx.x * blockDim.x + threadIdx.x;
    if (v < NNODES) {
        int dofs = g_deg_out[v]; if (dofs < 1) dofs = 1;
        int dins = g_deg_in[v];  if (dins < 1) dins = 1;
        g_norm_s[v] = rsqrtf((float)dofs);
        g_norm_d[v] = rsqrtf((float)dins);
    }
}

// ---------------- 2-level exclusive scan of deg_in -> row_ptr ----------------
// 1024 chunks of 49 elements (1024*49 = 50176 >= 50000)
__global__ void scan1_kernel() {
    __shared__ int s[1024];
    int t = threadIdx.x;
    int base = t * 49;
    int v = 0;
    for (int i = 0; i < 49; i++) {
        int idx = base + i;
        if (idx < NNODES) v += g_deg_in[idx];
    }
    s[t] = v;
    __syncthreads();
    int val = v;
    for (int off = 1; off < 1024; off <<= 1) {
        int x = (t >= off) ? s[t - off] : 0;
        __syncthreads();
        s[t] += x;
        __syncthreads();
    }
    int incl = s[t];
    g_chunk_off[t] = incl - val;               // exclusive chunk offset
    if (t == 1023) g_row_ptr[NNODES] = incl;   // = NEDGES
}

__global__ void scan2_kernel() {
    __shared__ int s[64];
    int c = blockIdx.x, t = threadIdx.x;
    int idx = c * 49 + t;
    int v = (t < 49 && idx < NNODES) ? g_deg_in[idx] : 0;
    s[t] = v;
    __syncthreads();
    for (int off = 1; off < 64; off <<= 1) {
        int x = (t >= off) ? s[t - off] : 0;
        __syncthreads();
        s[t] += x;
        __syncthreads();
    }
    if (t < 49 && idx < NNODES) {
        int excl = g_chunk_off[c] + s[t] - v;
        g_row_ptr[idx] = excl;
        g_cursor[idx]  = excl;
    }
}

__global__ void csr_fill_kernel(const int* __restrict__ src, const int* __restrict__ dst) {
    int e = blockIdx.x * blockDim.x + threadIdx.x;
    if (e < NEDGES) {
        int d = dst[e];
        int pos = atomicAdd(&g_cursor[d], 1);
        g_csr_src[pos] = src[e];
    }
}

// ---------------- embedding pooling (warp per node) --------------------------
__global__ void embed_kernel(const int* __restrict__ feats, const float* __restrict__ emb) {
    int gt   = blockIdx.x * blockDim.x + threadIdx.x;
    int node = gt >> 5;
    int lane = gt & 31;
    if (node >= NNODES) return;

    int tok = feats[node * SEQLEN + lane];
    int cnt = __popc(__ballot_sync(0xffffffffu, tok != 0));
    if (cnt < 1) cnt = 1;

    float4 s  = make_float4(0.f, 0.f, 0.f, 0.f);
    float4 mx = make_float4(-INFINITY, -INFINITY, -INFINITY, -INFINITY);

#pragma unroll
    for (int t = 0; t < 32; t++) {
        int tk = __shfl_sync(0xffffffffu, tok, t);
        float4 v = make_float4(0.f, 0.f, 0.f, 0.f);
        if (tk != 0) v = *(const float4*)&emb[(size_t)tk * EMBD + lane * 4];
        s.x += v.x; s.y += v.y; s.z += v.z; s.w += v.w;
        mx.x = fmaxf(mx.x, v.x); mx.y = fmaxf(mx.y, v.y);
        mx.z = fmaxf(mx.z, v.z); mx.w = fmaxf(mx.w, v.w);
    }
    float inv = 1.0f / (float)cnt;
    float4 h1 = make_float4(s.x * inv, s.y * inv, s.z * inv, s.w * inv);
    size_t base = (size_t)node * INFEAT;
    *(float4*)&g_h[base + lane * 4]        = h1;
    *(float4*)&g_h[base + EMBD + lane * 4] = mx;
}

// ---------------- GEMM1: hws1 = (h @ W1) * norm_s[row] -----------------------
#define BM 64
#define BN 64
#define BK 16
__global__ void gemm1_kernel(const float* __restrict__ B /* W1 [256,256] */) {
    __shared__ __align__(16) float As[BK][BM];
    __shared__ __align__(16) float Bs[BK][BN];
    int tid = threadIdx.x;
    int bm = blockIdx.x * BM, bn = blockIdx.y * BN;
    int tx = tid & 15, ty = tid >> 4;

    float acc[4][4] = {};

    for (int k0 = 0; k0 < NHID; k0 += BK) {
        {   // load A tile (64x16), transposed into As[k][m]
            int r = tid >> 2, c = (tid & 3) * 4;
            float4 a = make_float4(0.f, 0.f, 0.f, 0.f);
            if (bm + r < NNODES)
                a = *(const float4*)&g_h[(size_t)(bm + r) * INFEAT + k0 + c];
            As[c + 0][r] = a.x; As[c + 1][r] = a.y;
            As[c + 2][r] = a.z; As[c + 3][r] = a.w;
        }
        {   // load B tile (16x64)
            int r = tid >> 4, c = (tid & 15) * 4;
            *(float4*)&Bs[r][c] = *(const float4*)&B[(size_t)(k0 + r) * NHID + bn + c];
        }
        __syncthreads();
#pragma unroll
        for (int k = 0; k < BK; k++) {
            float4 ra = *(const float4*)&As[k][ty * 4];
            float4 rb = *(const float4*)&Bs[k][tx * 4];
            float a4[4] = {ra.x, ra.y, ra.z, ra.w};
            float b4[4] = {rb.x, rb.y, rb.z, rb.w};
#pragma unroll
            for (int i = 0; i < 4; i++)
#pragma unroll
                for (int j = 0; j < 4; j++)
                    acc[i][j] += a4[i] * b4[j];
        }
        __syncthreads();
    }

#pragma unroll
    for (int i = 0; i < 4; i++) {
        int row = bm + ty * 4 + i;
        if (row < NNODES) {
            float ns = g_norm_s[row];
            float4 o = make_float4(acc[i][0] * ns, acc[i][1] * ns,
                                   acc[i][2] * ns, acc[i][3] * ns);
            *(float4*)&g_hws1[(size_t)row * NHID + bn + tx * 4] = o;
        }
    }
}

// ---------------- agg layer 1: out1 = relu(segsum(hws1[src]) * norm_d + b1) --
__global__ void agg1_kernel(const float* __restrict__ b1) {
    int gt    = blockIdx.x * blockDim.x + threadIdx.x;
    int node  = gt >> 6;           // 64 threads per node
    int lane  = gt & 63;
    if (node >= NNODES) return;

    int beg = g_row_ptr[node], end = g_row_ptr[node + 1];
    float4 acc = make_float4(0.f, 0.f, 0.f, 0.f);
    for (int e = beg; e < end; e++) {
        int s = g_csr_src[e];
        float4 v = *(const float4*)&g_hws1[(size_t)s * NHID + lane * 4];
        acc.x += v.x; acc.y += v.y; acc.z += v.z; acc.w += v.w;
    }
    float nd = g_norm_d[node];
    float4 bb = *(const float4*)&b1[lane * 4];
    float4 o;
    o.x = fmaxf(acc.x * nd + bb.x, 0.f);
    o.y = fmaxf(acc.y * nd + bb.y, 0.f);
    o.z = fmaxf(acc.z * nd + bb.z, 0.f);
    o.w = fmaxf(acc.w * nd + bb.w, 0.f);
    *(float4*)&g_out1[(size_t)node * NHID + lane * 4] = o;
}

// ---------------- GEMM2: hws2 = (out1 @ W2) * norm_s -------------------------
__global__ void gemm2_kernel(const float* __restrict__ W2) {
    __shared__ __align__(16) float Ws[NHID * NCLS];   // 40 KB
    for (int i = threadIdx.x; i < (NHID * NCLS) / 4; i += blockDim.x)
        ((float4*)Ws)[i] = ((const float4*)W2)[i];
    __syncthreads();

    int row = blockIdx.x * blockDim.x + threadIdx.x;
    if (row >= NNODES) return;

    float acc[NCLS] = {};
    const float* a = &g_out1[(size_t)row * NHID];
    for (int k0 = 0; k0 < NHID; k0 += 4) {
        float4 av = *(const float4*)&a[k0];
        float a4[4] = {av.x, av.y, av.z, av.w};
#pragma unroll
        for (int kk = 0; kk < 4; kk++) {
            const float* w = &Ws[(k0 + kk) * NCLS];
            float av1 = a4[kk];
#pragma unroll
            for (int c = 0; c < NCLS; c++) acc[c] += av1 * w[c];
        }
    }
    float ns = g_norm_s[row];
    float* o = &g_hws2[(size_t)row * NCLS];
#pragma unroll
    for (int c = 0; c < NCLS; c++) o[c] = acc[c] * ns;
}

// ---------------- agg layer 2: out = segsum(hws2[src]) * norm_d + b2 ---------
__global__ void agg2_kernel(const float* __restrict__ b2, float* __restrict__ out) {
    int gt   = blockIdx.x * blockDim.x + threadIdx.x;
    int node = gt >> 5;            // warp per node
    int lane = gt & 31;
    if (node >= NNODES) return;

    int beg = g_row_ptr[node], end = g_row_ptr[node + 1];
    float a0 = 0.f, a1 = 0.f;
    for (int e = beg; e < end; e++) {
        int s = g_csr_src[e];
        const float* r = &g_hws2[(size_t)s * NCLS];
        a0 += r[lane];
        if (lane < 8) a1 += r[32 + lane];
    }
    float nd = g_norm_d[node];
    out[(size_t)node * NCLS + lane] = a0 * nd + b2[lane];
    if (lane < 8)
        out[(size_t)node * NCLS + 32 + lane] = a1 * nd + b2[32 + lane];
}

// ---------------- launch ------------------------------------------------------
extern "C" void kernel_launch(void* const* d_in, const int* in_sizes, int n_in,
                              void* d_out, int out_size) {
    const int*   feats = (const int*)d_in[0];
    const int*   src   = (const int*)d_in[1];
    const int*   dst   = (const int*)d_in[2];
    const float* emb   = (const float*)d_in[3];
    const float* W1    = (const float*)d_in[4];
    const float* b1    = (const float*)d_in[5];
    const float* W2    = (const float*)d_in[6];
    const float* b2    = (const float*)d_in[7];
    float*       out   = (float*)d_out;

    zero_degs_kernel<<<(NNODES + 511) / 512, 512>>>();
    degree_kernel<<<(NEDGES + 511) / 512, 512>>>(src, dst);
    norm_kernel<<<(NNODES + 255) / 256, 256>>>();
    scan1_kernel<<<1, 1024>>>();
    scan2_kernel<<<1024, 64>>>();
    csr_fill_kernel<<<(NEDGES + 511) / 512, 512>>>(src, dst);

    embed_kernel<<<(NNODES * 32 + 255) / 256, 256>>>(feats, emb);

    dim3 g1((NNODES + BM - 1) / BM, NHID / BN);
    gemm1_kernel<<<g1, 256>>>(W1);

    agg1_kernel<<<(NNODES * 64 + 255) / 256, 256>>>(b1);

    gemm2_kernel<<<(NNODES + 255) / 256, 256>>>(W2);

    agg2_kernel<<<(NNODES * 32 + 255) / 256, 256>>>(b2, out);
}

// round 2
// speedup vs baseline: 1.0221x; 1.0221x over previous
#include <cuda_runtime.h>
#include <math.h>

#define NNODES 50000
#define NEDGES 800000
#define SEQLEN 32
#define EMBD   128
#define INFEAT 256
#define NHID   256
#define NCLS   40

#define CHUNK   512
#define NCHUNK  98      // 98*512 = 50176 >= 50000

typedef unsigned long long ull;

// ---------------- scratch (device globals; no allocation allowed) ------------
__device__ int   g_deg_out[NNODES];
__device__ int   g_deg_in[NNODES];
__device__ float g_norm_s[NNODES];
__device__ float g_norm_d[NNODES];
__device__ int   g_row_ptr[NNODES + 1];
__device__ int   g_cursor[NNODES];
__device__ int   g_chunk_sum[NCHUNK];
__device__ int   g_chunk_off[NCHUNK];
__device__ int   g_csr_src[NEDGES];
__device__ float g_h[(size_t)NNODES * INFEAT];     // pooled embeddings [N,256]
__device__ float g_hws1[(size_t)NNODES * NHID];    // (h@W1)*norm_s
__device__ float g_out1[(size_t)NNODES * NHID];    // relu(agg*norm_d + b1)
__device__ float g_hws2[(size_t)NNODES * NCLS];    // (out1@W2)*norm_s

// ---------------- f32x2 helpers ----------------------------------------------
__device__ __forceinline__ ull ffma2(ull a, ull b, ull c) {
    ull d;
    asm("fma.rn.f32x2 %0, %1, %2, %3;" : "=l"(d) : "l"(a), "l"(b), "l"(c));
    return d;
}
__device__ __forceinline__ ull dup2(float x) {
    ull d;
    asm("mov.b64 %0, {%1, %1};" : "=l"(d) : "f"(x));
    return d;
}
__device__ __forceinline__ void unpack2(ull v, float& lo, float& hi) {
    asm("mov.b64 {%0, %1}, %2;" : "=f"(lo), "=f"(hi) : "l"(v));
}

// ---------------- degree ------------------------------------------------------
__global__ void zero_degs_kernel() {
    int i = blockIdx.x * blockDim.x + threadIdx.x;
    if (i < NNODES) { g_deg_out[i] = 0; g_deg_in[i] = 0; }
}

__global__ void degree_kernel(const int* __restrict__ src, const int* __restrict__ dst) {
    int e = blockIdx.x * blockDim.x + threadIdx.x;
    if (e < NEDGES) {
        atomicAdd(&g_deg_out[src[e]], 1);
        atomicAdd(&g_deg_in[dst[e]], 1);
    }
}

// ---------------- 3-stage coalesced scan of deg_in -> row_ptr, + norms -------
__global__ void scanA_kernel() {   // 98 blocks x 512: chunk sums
    __shared__ int s[CHUNK];
    int t = threadIdx.x, b = blockIdx.x;
    int idx = b * CHUNK + t;
    int v = (idx < NNODES) ? g_deg_in[idx] : 0;
    s[t] = v;
    __syncthreads();
    for (int off = CHUNK / 2; off > 0; off >>= 1) {
        if (t < off) s[t] += s[t + off];
        __syncthreads();
    }
    if (t == 0) g_chunk_sum[b] = s[0];
}

__global__ void scanB_kernel() {   // 1 block x 128: scan 98 chunk sums
    __shared__ int s[128];
    int t = threadIdx.x;
    int v = (t < NCHUNK) ? g_chunk_sum[t] : 0;
    s[t] = v;
    __syncthreads();
    for (int off = 1; off < 128; off <<= 1) {
        int x = (t >= off) ? s[t - off] : 0;
        __syncthreads();
        s[t] += x;
        __syncthreads();
    }
    if (t < NCHUNK) g_chunk_off[t] = s[t] - v;   // exclusive
    if (t == 0) g_row_ptr[NNODES] = NEDGES;
}

__global__ void scanC_kernel() {   // 98 blocks x 512: intra-chunk scan + norms
    __shared__ int s[CHUNK];
    int t = threadIdx.x, b = blockIdx.x;
    int idx = b * CHUNK + t;
    int v = (idx < NNODES) ? g_deg_in[idx] : 0;
    s[t] = v;
    __syncthreads();
    for (int off = 1; off < CHUNK; off <<= 1) {
        int x = (t >= off) ? s[t - off] : 0;
        __syncthreads();
        s[t] += x;
        __syncthreads();
    }
    if (idx < NNODES) {
        int excl = g_chunk_off[b] + s[t] - v;
        g_row_ptr[idx] = excl;
        g_cursor[idx]  = excl;
        int dins = v; if (dins < 1) dins = 1;
        int dofs = g_deg_out[idx]; if (dofs < 1) dofs = 1;
        g_norm_d[idx] = rsqrtf((float)dins);
        g_norm_s[idx] = rsqrtf((float)dofs);
    }
}

__global__ void csr_fill_kernel(const int* __restrict__ src, const int* __restrict__ dst) {
    int e = blockIdx.x * blockDim.x + threadIdx.x;
    if (e < NEDGES) {
        int d = dst[e];
        int pos = atomicAdd(&g_cursor[d], 1);
        g_csr_src[pos] = src[e];
    }
}

// ---------------- embedding pooling (warp per node) --------------------------
__global__ void embed_kernel(const int* __restrict__ feats, const float* __restrict__ emb) {
    int gt   = blockIdx.x * blockDim.x + threadIdx.x;
    int node = gt >> 5;
    int lane = gt & 31;
    if (node >= NNODES) return;

    int tok = feats[node * SEQLEN + lane];
    int cnt = __popc(__ballot_sync(0xffffffffu, tok != 0));
    if (cnt < 1) cnt = 1;

    float4 s  = make_float4(0.f, 0.f, 0.f, 0.f);
    float4 mx = make_float4(-INFINITY, -INFINITY, -INFINITY, -INFINITY);

#pragma unroll
    for (int t = 0; t < 32; t++) {
        int tk = __shfl_sync(0xffffffffu, tok, t);
        float4 v = make_float4(0.f, 0.f, 0.f, 0.f);
        if (tk != 0) v = *(const float4*)&emb[(size_t)tk * EMBD + lane * 4];
        s.x += v.x; s.y += v.y; s.z += v.z; s.w += v.w;
        mx.x = fmaxf(mx.x, v.x); mx.y = fmaxf(mx.y, v.y);
        mx.z = fmaxf(mx.z, v.z); mx.w = fmaxf(mx.w, v.w);
    }
    float inv = 1.0f / (float)cnt;
    float4 h1 = make_float4(s.x * inv, s.y * inv, s.z * inv, s.w * inv);
    size_t base = (size_t)node * INFEAT;
    *(float4*)&g_h[base + lane * 4]        = h1;
    *(float4*)&g_h[base + EMBD + lane * 4] = mx;
}

// ---------------- GEMM1: hws1 = (h @ W1) * norm_s[row], f32x2 128x128 --------
#define BM1 128
#define BN1 128
#define BK1 8
__global__ __launch_bounds__(256, 2)
void gemm1_kernel(const float* __restrict__ W1) {
    // As stores each A value DUPLICATED ({a,a}) so the inner loop needs no packing.
    __shared__ __align__(16) float As[2][BK1][2 * BM1];   // 16 KB
    __shared__ __align__(16) float Bs[2][BK1][BN1];       //  8 KB

    int tid = threadIdx.x;
    int bm = blockIdx.x * BM1, bn = blockIdx.y * BN1;
    int tx = tid & 15, ty = tid >> 4;

    // loader coords
    int ar = tid >> 1, akq = (tid & 1) * 4;      // A: row ar (0..127), k quad
    int br = tid >> 5, bc = (tid & 31) * 4;      // B: k row br (0..7), col quad

    ull acc[8][4];
#pragma unroll
    for (int i = 0; i < 8; i++)
#pragma unroll
        for (int j = 0; j < 4; j++) acc[i][j] = 0ull;

    const int T = INFEAT / BK1;   // 32

    // prologue: load tile 0
    float4 aR, bR;
    {
        int row = bm + ar;
        aR = make_float4(0.f, 0.f, 0.f, 0.f);
        if (row < NNODES) aR = *(const float4*)&g_h[(size_t)row * INFEAT + akq];
        bR = *(const float4*)&W1[(size_t)br * NHID + bn + bc];
    }
    {
        float a4[4] = {aR.x, aR.y, aR.z, aR.w};
#pragma unroll
        for (int j = 0; j < 4; j++) {
            As[0][akq + j][2 * ar]     = a4[j];
            As[0][akq + j][2 * ar + 1] = a4[j];
        }
        *(float4*)&Bs[0][br][bc] = bR;
    }
    __syncthreads();

    for (int t = 0; t < T; t++) {
        int cur = t & 1, nxt = cur ^ 1;
        if (t + 1 < T) {
            int k0 = (t + 1) * BK1;
            int row = bm + ar;
            aR = make_float4(0.f, 0.f, 0.f, 0.f);
            if (row < NNODES) aR = *(const float4*)&g_h[(size_t)row * INFEAT + k0 + akq];
            bR = *(const float4*)&W1[(size_t)(k0 + br) * NHID + bn + bc];
        }

#pragma unroll
        for (int k = 0; k < BK1; k++) {
            const ull* ap = (const ull*)&As[cur][k][ty * 16];
            const ull* bp = (const ull*)&Bs[cur][k][tx * 8];
            ull ad[8], bv[4];
#pragma unroll
            for (int i = 0; i < 8; i++) ad[i] = ap[i];
#pragma unroll
            for (int j = 0; j < 4; j++) bv[j] = bp[j];
#pragma unroll
            for (int i = 0; i < 8; i++)
#pragma unroll
                for (int j = 0; j < 4; j++)
                    acc[i][j] = ffma2(ad[i], bv[j], acc[i][j]);
        }

        if (t + 1 < T) {
            float a4[4] = {aR.x, aR.y, aR.z, aR.w};
#pragma unroll
            for (int j = 0; j < 4; j++) {
                As[nxt][akq + j][2 * ar]     = a4[j];
                As[nxt][akq + j][2 * ar + 1] = a4[j];
            }
            *(float4*)&Bs[nxt][br][bc] = bR;
        }
        __syncthreads();
    }

    // epilogue: scale by norm_s, store
#pragma unroll
    for (int i = 0; i < 8; i++) {
        int row = bm + ty * 8 + i;
        if (row < NNODES) {
            float ns = g_norm_s[row];
            float o[8];
#pragma unroll
            for (int j = 0; j < 4; j++) unpack2(acc[i][j], o[2 * j], o[2 * j + 1]);
#pragma unroll
            for (int j = 0; j < 8; j++) o[j] *= ns;
            float* dst = &g_hws1[(size_t)row * NHID + bn + tx * 8];
            *(float4*)&dst[0] = make_float4(o[0], o[1], o[2], o[3]);
            *(float4*)&dst[4] = make_float4(o[4], o[5], o[6], o[7]);
        }
    }
}

// ---------------- agg layer 1: out1 = relu(segsum(hws1[src]) * norm_d + b1) --
__global__ void agg1_kernel(const float* __restrict__ b1) {
    int gt    = blockIdx.x * blockDim.x + threadIdx.x;
    int node  = gt >> 6;           // 64 threads per node
    int lane  = gt & 63;
    if (node >= NNODES) return;

    int beg = g_row_ptr[node], end = g_row_ptr[node + 1];
    float4 acc = make_float4(0.f, 0.f, 0.f, 0.f);
    int e = beg;
    for (; e + 1 < end; e += 2) {
        int s0 = g_csr_src[e], s1 = g_csr_src[e + 1];
        float4 v0 = *(const float4*)&g_hws1[(size_t)s0 * NHID + lane * 4];
        float4 v1 = *(const float4*)&g_hws1[(size_t)s1 * NHID + lane * 4];
        acc.x += v0.x + v1.x; acc.y += v0.y + v1.y;
        acc.z += v0.z + v1.z; acc.w += v0.w + v1.w;
    }
    if (e < end) {
        int s0 = g_csr_src[e];
        float4 v0 = *(const float4*)&g_hws1[(size_t)s0 * NHID + lane * 4];
        acc.x += v0.x; acc.y += v0.y; acc.z += v0.z; acc.w += v0.w;
    }
    float nd = g_norm_d[node];
    float4 bb = *(const float4*)&b1[lane * 4];
    float4 o;
    o.x = fmaxf(acc.x * nd + bb.x, 0.f);
    o.y = fmaxf(acc.y * nd + bb.y, 0.f);
    o.z = fmaxf(acc.z * nd + bb.z, 0.f);
    o.w = fmaxf(acc.w * nd + bb.w, 0.f);
    *(float4*)&g_out1[(size_t)node * NHID + lane * 4] = o;
}

// ---------------- GEMM2: hws2 = (out1 @ W2) * norm_s, f32x2 ------------------
__global__ __launch_bounds__(256)
void gemm2_kernel(const float* __restrict__ W2) {
    __shared__ __align__(16) float Ws[NHID * NCLS];   // 40 KB
    for (int i = threadIdx.x; i < (NHID * NCLS) / 4; i += blockDim.x)
        ((float4*)Ws)[i] = ((const float4*)W2)[i];
    __syncthreads();

    int row = blockIdx.x * blockDim.x + threadIdx.x;
    if (row >= NNODES) return;

    ull acc[NCLS / 2];
#pragma unroll
    for (int c = 0; c < NCLS / 2; c++) acc[c] = 0ull;

    const float* a = &g_out1[(size_t)row * NHID];
    for (int k0 = 0; k0 < NHID; k0 += 4) {
        float4 av = *(const float4*)&a[k0];
        float a4[4] = {av.x, av.y, av.z, av.w};
#pragma unroll
        for (int kk = 0; kk < 4; kk++) {
            ull ad = dup2(a4[kk]);
            const ull* w = (const ull*)&Ws[(k0 + kk) * NCLS];
#pragma unroll
            for (int c = 0; c < NCLS / 2; c++) acc[c] = ffma2(ad, w[c], acc[c]);
        }
    }
    float ns = g_norm_s[row];
    float o[NCLS];
#pragma unroll
    for (int c = 0; c < NCLS / 2; c++) unpack2(acc[c], o[2 * c], o[2 * c + 1]);
    float* dst = &g_hws2[(size_t)row * NCLS];
#pragma unroll
    for (int c = 0; c < NCLS / 4; c++)
        ((float4*)dst)[c] = make_float4(o[4 * c] * ns, o[4 * c + 1] * ns,
                                        o[4 * c + 2] * ns, o[4 * c + 3] * ns);
}

// ---------------- agg layer 2: out = segsum(hws2[src]) * norm_d + b2 ---------
__global__ void agg2_kernel(const float* __restrict__ b2, float* __restrict__ out) {
    int gt   = blockIdx.x * blockDim.x + threadIdx.x;
    int node = gt >> 5;            // warp per node
    int lane = gt & 31;
    if (node >= NNODES) return;

    int beg = g_row_ptr[node], end = g_row_ptr[node + 1];
    float a0 = 0.f, a1 = 0.f;
    for (int e = beg; e < end; e++) {
        int s = g_csr_src[e];
        const float* r = &g_hws2[(size_t)s * NCLS];
        a0 += r[lane];
        if (lane < 8) a1 += r[32 + lane];
    }
    float nd = g_norm_d[node];
    out[(size_t)node * NCLS + lane] = a0 * nd + b2[lane];
    if (lane < 8)
        out[(size_t)node * NCLS + 32 + lane] = a1 * nd + b2[32 + lane];
}

// ---------------- launch ------------------------------------------------------
static cudaStream_t g_s2 = 0;
static cudaEvent_t  g_ev_fork = 0, g_ev_join = 0;

extern "C" void kernel_launch(void* const* d_in, const int* in_sizes, int n_in,
                              void* d_out, int out_size) {
    const int*   feats = (const int*)d_in[0];
    const int*   src   = (const int*)d_in[1];
    const int*   dst   = (const int*)d_in[2];
    const float* emb   = (const float*)d_in[3];
    const float* W1    = (const float*)d_in[4];
    const float* b1    = (const float*)d_in[5];
    const float* W2    = (const float*)d_in[6];
    const float* b2    = (const float*)d_in[7];
    float*       out   = (float*)d_out;

    if (!g_s2) {   // resource creation only (host-side, no device memory)
        cudaStreamCreateWithFlags(&g_s2, cudaStreamNonBlocking);
        cudaEventCreateWithFlags(&g_ev_fork, cudaEventDisableTiming);
        cudaEventCreateWithFlags(&g_ev_join, cudaEventDisableTiming);
    }

    // fork: embedding pooling runs concurrently with CSR construction
    cudaEventRecord(g_ev_fork, 0);
    cudaStreamWaitEvent(g_s2, g_ev_fork, 0);
    embed_kernel<<<(NNODES * 32 + 255) / 256, 256, 0, g_s2>>>(feats, emb);
    cudaEventRecord(g_ev_join, g_s2);

    // CSR build chain on default stream
    zero_degs_kernel<<<(NNODES + 511) / 512, 512>>>();
    degree_kernel<<<(NEDGES + 511) / 512, 512>>>(src, dst);
    scanA_kernel<<<NCHUNK, CHUNK>>>();
    scanB_kernel<<<1, 128>>>();
    scanC_kernel<<<NCHUNK, CHUNK>>>();
    csr_fill_kernel<<<(NEDGES + 511) / 512, 512>>>(src, dst);

    // join: gemm1 needs g_h (embed) and g_norm_s (scanC)
    cudaStreamWaitEvent(0, g_ev_join, 0);

    dim3 g1((NNODES + BM1 - 1) / BM1, NHID / BN1);
    gemm1_kernel<<<g1, 256>>>(W1);

    agg1_kernel<<<(NNODES * 64 + 255) / 256, 256>>>(b1);

    gemm2_kernel<<<(NNODES + 255) / 256, 256>>>(W2);

    agg2_kernel<<<(NNODES * 32 + 255) / 256, 256>>>(b2, out);
}

// round 3
// speedup vs baseline: 1.1231x; 1.0988x over previous
#include <cuda_runtime.h>
#include <cuda_bf16.h>
#include <math.h>

#define NNODES 50000
#define NEDGES 800000
#define SEQLEN 32
#define EMBD   128
#define INFEAT 256
#define NHID   256
#define NCLS   40

#define CHUNK   512
#define NCHUNK  98      // 98*512 = 50176 >= 50000

typedef unsigned long long ull;

// ---------------- scratch (device globals; no allocation allowed) ------------
__device__ int   g_deg_out[NNODES];
__device__ int   g_deg_in[NNODES];
__device__ float g_norm_s[NNODES];
__device__ float g_norm_d[NNODES];
__device__ int   g_row_ptr[NNODES + 1];
__device__ int   g_cursor[NNODES];
__device__ int   g_chunk_sum[NCHUNK];
__device__ int   g_chunk_off[NCHUNK];
__device__ int   g_csr_src[NEDGES];
__device__ float g_h[(size_t)NNODES * INFEAT];          // pooled embeddings [N,256]
__device__ __align__(16) __nv_bfloat16 g_hw1b[(size_t)NNODES * NHID];  // h@W1 (bf16, no norm)
__device__ float g_out1[(size_t)NNODES * NHID];         // relu(agg*norm_d + b1)
__device__ float g_hws2[(size_t)NNODES * NCLS];         // (out1@W2)*norm_s

// ---------------- f32x2 helpers ----------------------------------------------
__device__ __forceinline__ ull ffma2(ull a, ull b, ull c) {
    ull d;
    asm("fma.rn.f32x2 %0, %1, %2, %3;" : "=l"(d) : "l"(a), "l"(b), "l"(c));
    return d;
}
__device__ __forceinline__ ull dup2(float x) {
    ull d;
    asm("mov.b64 %0, {%1, %1};" : "=l"(d) : "f"(x));
    return d;
}
__device__ __forceinline__ void unpack2(ull v, float& lo, float& hi) {
    asm("mov.b64 {%0, %1}, %2;" : "=f"(lo), "=f"(hi) : "l"(v));
}

// ---------------- degree ------------------------------------------------------
__global__ void zero_degs_kernel() {
    int i = blockIdx.x * blockDim.x + threadIdx.x;
    if (i < NNODES) { g_deg_out[i] = 0; g_deg_in[i] = 0; }
}

__global__ void degree_kernel(const int* __restrict__ src, const int* __restrict__ dst) {
    int e = blockIdx.x * blockDim.x + threadIdx.x;
    if (e < NEDGES) {
        atomicAdd(&g_deg_out[src[e]], 1);
        atomicAdd(&g_deg_in[dst[e]], 1);
    }
}

// ---------------- 3-stage coalesced scan of deg_in -> row_ptr, + norms -------
__global__ void scanA_kernel() {
    __shared__ int s[CHUNK];
    int t = threadIdx.x, b = blockIdx.x;
    int idx = b * CHUNK + t;
    int v = (idx < NNODES) ? g_deg_in[idx] : 0;
    s[t] = v;
    __syncthreads();
    for (int off = CHUNK / 2; off > 0; off >>= 1) {
        if (t < off) s[t] += s[t + off];
        __syncthreads();
    }
    if (t == 0) g_chunk_sum[b] = s[0];
}

__global__ void scanB_kernel() {
    __shared__ int s[128];
    int t = threadIdx.x;
    int v = (t < NCHUNK) ? g_chunk_sum[t] : 0;
    s[t] = v;
    __syncthreads();
    for (int off = 1; off < 128; off <<= 1) {
        int x = (t >= off) ? s[t - off] : 0;
        __syncthreads();
        s[t] += x;
        __syncthreads();
    }
    if (t < NCHUNK) g_chunk_off[t] = s[t] - v;
    if (t == 0) g_row_ptr[NNODES] = NEDGES;
}

__global__ void scanC_kernel() {
    __shared__ int s[CHUNK];
    int t = threadIdx.x, b = blockIdx.x;
    int idx = b * CHUNK + t;
    int v = (idx < NNODES) ? g_deg_in[idx] : 0;
    s[t] = v;
    __syncthreads();
    for (int off = 1; off < CHUNK; off <<= 1) {
        int x = (t >= off) ? s[t - off] : 0;
        __syncthreads();
        s[t] += x;
        __syncthreads();
    }
    if (idx < NNODES) {
        int excl = g_chunk_off[b] + s[t] - v;
        g_row_ptr[idx] = excl;
        g_cursor[idx]  = excl;
        int dins = v; if (dins < 1) dins = 1;
        int dofs = g_deg_out[idx]; if (dofs < 1) dofs = 1;
        g_norm_d[idx] = rsqrtf((float)dins);
        g_norm_s[idx] = rsqrtf((float)dofs);
    }
}

__global__ void csr_fill_kernel(const int* __restrict__ src, const int* __restrict__ dst) {
    int e = blockIdx.x * blockDim.x + threadIdx.x;
    if (e < NEDGES) {
        int d = dst[e];
        int pos = atomicAdd(&g_cursor[d], 1);
        g_csr_src[pos] = src[e];
    }
}

// ---------------- embedding pooling (warp per node) --------------------------
__global__ void embed_kernel(const int* __restrict__ feats, const float* __restrict__ emb) {
    int gt   = blockIdx.x * blockDim.x + threadIdx.x;
    int node = gt >> 5;
    int lane = gt & 31;
    if (node >= NNODES) return;

    int tok = feats[node * SEQLEN + lane];
    int cnt = __popc(__ballot_sync(0xffffffffu, tok != 0));
    if (cnt < 1) cnt = 1;

    float4 s  = make_float4(0.f, 0.f, 0.f, 0.f);
    float4 mx = make_float4(-INFINITY, -INFINITY, -INFINITY, -INFINITY);

#pragma unroll
    for (int t = 0; t < 32; t++) {
        int tk = __shfl_sync(0xffffffffu, tok, t);
        float4 v = make_float4(0.f, 0.f, 0.f, 0.f);
        if (tk != 0) v = *(const float4*)&emb[(size_t)tk * EMBD + lane * 4];
        s.x += v.x; s.y += v.y; s.z += v.z; s.w += v.w;
        mx.x = fmaxf(mx.x, v.x); mx.y = fmaxf(mx.y, v.y);
        mx.z = fmaxf(mx.z, v.z); mx.w = fmaxf(mx.w, v.w);
    }
    float inv = 1.0f / (float)cnt;
    float4 h1 = make_float4(s.x * inv, s.y * inv, s.z * inv, s.w * inv);
    size_t base = (size_t)node * INFEAT;
    *(float4*)&g_h[base + lane * 4]        = h1;
    *(float4*)&g_h[base + EMBD + lane * 4] = mx;
}

// ---------------- GEMM1: g_hw1b = bf16(h @ W1), f32x2 core -------------------
#define BM1 128
#define BN1 128
#define BK1 8
__global__ __launch_bounds__(256, 2)
void gemm1_kernel(const float* __restrict__ W1) {
    __shared__ __align__(16) float As[2][BK1][2 * BM1];   // duplicated A
    __shared__ __align__(16) float Bs[2][BK1][BN1];

    int tid = threadIdx.x;
    int bm = blockIdx.x * BM1, bn = blockIdx.y * BN1;
    int tx = tid & 15, ty = tid >> 4;

    int ar = tid >> 1, akq = (tid & 1) * 4;
    int br = tid >> 5, bc = (tid & 31) * 4;

    ull acc[8][4];
#pragma unroll
    for (int i = 0; i < 8; i++)
#pragma unroll
        for (int j = 0; j < 4; j++) acc[i][j] = 0ull;

    const int T = INFEAT / BK1;

    float4 aR, bR;
    {
        int row = bm + ar;
        aR = make_float4(0.f, 0.f, 0.f, 0.f);
        if (row < NNODES) aR = *(const float4*)&g_h[(size_t)row * INFEAT + akq];
        bR = *(const float4*)&W1[(size_t)br * NHID + bn + bc];
    }
    {
        float a4[4] = {aR.x, aR.y, aR.z, aR.w};
#pragma unroll
        for (int j = 0; j < 4; j++) {
            As[0][akq + j][2 * ar]     = a4[j];
            As[0][akq + j][2 * ar + 1] = a4[j];
        }
        *(float4*)&Bs[0][br][bc] = bR;
    }
    __syncthreads();

    for (int t = 0; t < T; t++) {
        int cur = t & 1, nxt = cur ^ 1;
        if (t + 1 < T) {
            int k0 = (t + 1) * BK1;
            int row = bm + ar;
            aR = make_float4(0.f, 0.f, 0.f, 0.f);
            if (row < NNODES) aR = *(const float4*)&g_h[(size_t)row * INFEAT + k0 + akq];
            bR = *(const float4*)&W1[(size_t)(k0 + br) * NHID + bn + bc];
        }

#pragma unroll
        for (int k = 0; k < BK1; k++) {
            const ull* ap = (const ull*)&As[cur][k][ty * 16];
            const ull* bp = (const ull*)&Bs[cur][k][tx * 8];
            ull ad[8], bv[4];
#pragma unroll
            for (int i = 0; i < 8; i++) ad[i] = ap[i];
#pragma unroll
            for (int j = 0; j < 4; j++) bv[j] = bp[j];
#pragma unroll
            for (int i = 0; i < 8; i++)
#pragma unroll
                for (int j = 0; j < 4; j++)
                    acc[i][j] = ffma2(ad[i], bv[j], acc[i][j]);
        }

        if (t + 1 < T) {
            float a4[4] = {aR.x, aR.y, aR.z, aR.w};
#pragma unroll
            for (int j = 0; j < 4; j++) {
                As[nxt][akq + j][2 * ar]     = a4[j];
                As[nxt][akq + j][2 * ar + 1] = a4[j];
            }
            *(float4*)&Bs[nxt][br][bc] = bR;
        }
        __syncthreads();
    }

    // epilogue: convert to bf16 (no norm here; norm_s applied per-edge in agg1)
#pragma unroll
    for (int i = 0; i < 8; i++) {
        int row = bm + ty * 8 + i;
        if (row < NNODES) {
            float o[8];
#pragma unroll
            for (int j = 0; j < 4; j++) unpack2(acc[i][j], o[2 * j], o[2 * j + 1]);
            uint4 pk;
            __nv_bfloat162 p0 = __float22bfloat162_rn(make_float2(o[0], o[1]));
            __nv_bfloat162 p1 = __float22bfloat162_rn(make_float2(o[2], o[3]));
            __nv_bfloat162 p2 = __float22bfloat162_rn(make_float2(o[4], o[5]));
            __nv_bfloat162 p3 = __float22bfloat162_rn(make_float2(o[6], o[7]));
            pk.x = *(unsigned*)&p0; pk.y = *(unsigned*)&p1;
            pk.z = *(unsigned*)&p2; pk.w = *(unsigned*)&p3;
            *(uint4*)&g_hw1b[(size_t)row * NHID + bn + tx * 8] = pk;
        }
    }
}

// ---------------- agg layer 1 (bf16 messages, warp per node) -----------------
// out1 = relu( norm_d * segsum( norm_s[src] * bf16(hw1)[src] ) + b1 )
__global__ void agg1_kernel(const float* __restrict__ b1) {
    int gt   = blockIdx.x * blockDim.x + threadIdx.x;
    int node = gt >> 5;
    int lane = gt & 31;
    if (node >= NNODES) return;

    int beg = g_row_ptr[node], end = g_row_ptr[node + 1];
    float acc[8] = {0.f, 0.f, 0.f, 0.f, 0.f, 0.f, 0.f, 0.f};

    int e = beg;
    for (; e + 1 < end; e += 2) {
        int s0 = g_csr_src[e], s1 = g_csr_src[e + 1];
        float n0 = g_norm_s[s0], n1 = g_norm_s[s1];
        uint4 u0 = *(const uint4*)&g_hw1b[(size_t)s0 * NHID + lane * 8];
        uint4 u1 = *(const uint4*)&g_hw1b[(size_t)s1 * NHID + lane * 8];
        const unsigned* w0 = &u0.x;
        const unsigned* w1 = &u1.x;
#pragma unroll
        for (int j = 0; j < 4; j++) {
            float2 f0 = __bfloat1622float2(*(const __nv_bfloat162*)&w0[j]);
            float2 f1 = __bfloat1622float2(*(const __nv_bfloat162*)&w1[j]);
            acc[2 * j]     += f0.x * n0 + f1.x * n1;
            acc[2 * j + 1] += f0.y * n0 + f1.y * n1;
        }
    }
    if (e < end) {
        int s0 = g_csr_src[e];
        float n0 = g_norm_s[s0];
        uint4 u0 = *(const uint4*)&g_hw1b[(size_t)s0 * NHID + lane * 8];
        const unsigned* w0 = &u0.x;
#pragma unroll
        for (int j = 0; j < 4; j++) {
            float2 f0 = __bfloat1622float2(*(const __nv_bfloat162*)&w0[j]);
            acc[2 * j]     += f0.x * n0;
            acc[2 * j + 1] += f0.y * n0;
        }
    }

    float nd = g_norm_d[node];
    float* dst = &g_out1[(size_t)node * NHID + lane * 8];
    float4 bb0 = *(const float4*)&b1[lane * 8];
    float4 bb1 = *(const float4*)&b1[lane * 8 + 4];
    float4 o0, o1;
    o0.x = fmaxf(acc[0] * nd + bb0.x, 0.f);
    o0.y = fmaxf(acc[1] * nd + bb0.y, 0.f);
    o0.z = fmaxf(acc[2] * nd + bb0.z, 0.f);
    o0.w = fmaxf(acc[3] * nd + bb0.w, 0.f);
    o1.x = fmaxf(acc[4] * nd + bb1.x, 0.f);
    o1.y = fmaxf(acc[5] * nd + bb1.y, 0.f);
    o1.z = fmaxf(acc[6] * nd + bb1.z, 0.f);
    o1.w = fmaxf(acc[7] * nd + bb1.w, 0.f);
    *(float4*)&dst[0] = o0;
    *(float4*)&dst[4] = o1;
}

// ---------------- GEMM2: hws2 = (out1 @ W2) * norm_s, f32x2 ------------------
__global__ __launch_bounds__(256)
void gemm2_kernel(const float* __restrict__ W2) {
    __shared__ __align__(16) float Ws[NHID * NCLS];
    for (int i = threadIdx.x; i < (NHID * NCLS) / 4; i += blockDim.x)
        ((float4*)Ws)[i] = ((const float4*)W2)[i];
    __syncthreads();

    int row = blockIdx.x * blockDim.x + threadIdx.x;
    if (row >= NNODES) return;

    ull acc[NCLS / 2];
#pragma unroll
    for (int c = 0; c < NCLS / 2; c++) acc[c] = 0ull;

    const float* a = &g_out1[(size_t)row * NHID];
    for (int k0 = 0; k0 < NHID; k0 += 4) {
        float4 av = *(const float4*)&a[k0];
        float a4[4] = {av.x, av.y, av.z, av.w};
#pragma unroll
        for (int kk = 0; kk < 4; kk++) {
            ull ad = dup2(a4[kk]);
            const ull* w = (const ull*)&Ws[(k0 + kk) * NCLS];
#pragma unroll
            for (int c = 0; c < NCLS / 2; c++) acc[c] = ffma2(ad, w[c], acc[c]);
        }
    }
    float ns = g_norm_s[row];
    float o[NCLS];
#pragma unroll
    for (int c = 0; c < NCLS / 2; c++) unpack2(acc[c], o[2 * c], o[2 * c + 1]);
    float* dst = &g_hws2[(size_t)row * NCLS];
#pragma unroll
    for (int c = 0; c < NCLS / 4; c++)
        ((float4*)dst)[c] = make_float4(o[4 * c] * ns, o[4 * c + 1] * ns,
                                        o[4 * c + 2] * ns, o[4 * c + 3] * ns);
}

// ---------------- agg layer 2: out = segsum(hws2[src]) * norm_d + b2 ---------
__global__ void agg2_kernel(const float* __restrict__ b2, float* __restrict__ out) {
    int gt   = blockIdx.x * blockDim.x + threadIdx.x;
    int node = gt >> 5;
    int lane = gt & 31;
    if (node >= NNODES) return;

    int beg = g_row_ptr[node], end = g_row_ptr[node + 1];
    float a0 = 0.f, a1 = 0.f;
    for (int e = beg; e < end; e++) {
        int s = g_csr_src[e];
        const float* r = &g_hws2[(size_t)s * NCLS];
        a0 += r[lane];
        if (lane < 8) a1 += r[32 + lane];
    }
    float nd = g_norm_d[node];
    out[(size_t)node * NCLS + lane] = a0 * nd + b2[lane];
    if (lane < 8)
        out[(size_t)node * NCLS + 32 + lane] = a1 * nd + b2[32 + lane];
}

// ---------------- launch ------------------------------------------------------
static cudaStream_t g_s2 = 0;
static cudaEvent_t  g_ev_fork = 0, g_ev_join = 0;

extern "C" void kernel_launch(void* const* d_in, const int* in_sizes, int n_in,
                              void* d_out, int out_size) {
    const int*   feats = (const int*)d_in[0];
    const int*   src   = (const int*)d_in[1];
    const int*   dst   = (const int*)d_in[2];
    const float* emb   = (const float*)d_in[3];
    const float* W1    = (const float*)d_in[4];
    const float* b1    = (const float*)d_in[5];
    const float* W2    = (const float*)d_in[6];
    const float* b2    = (const float*)d_in[7];
    float*       out   = (float*)d_out;

    if (!g_s2) {
        cudaStreamCreateWithFlags(&g_s2, cudaStreamNonBlocking);
        cudaEventCreateWithFlags(&g_ev_fork, cudaEventDisableTiming);
        cudaEventCreateWithFlags(&g_ev_join, cudaEventDisableTiming);
    }

    // fork side stream for the CSR build chain
    cudaEventRecord(g_ev_fork, 0);
    cudaStreamWaitEvent(g_s2, g_ev_fork, 0);

    // main: embed -> gemm1 (launch idx 0 and 3, gemm1 lands on profiled slot)
    embed_kernel<<<(NNODES * 32 + 255) / 256, 256>>>(feats, emb);      // idx 0
    zero_degs_kernel<<<(NNODES + 511) / 512, 512, 0, g_s2>>>();        // idx 1
    degree_kernel<<<(NEDGES + 511) / 512, 512, 0, g_s2>>>(src, dst);   // idx 2
    dim3 g1((NNODES + BM1 - 1) / BM1, NHID / BN1);
    gemm1_kernel<<<g1, 256>>>(W1);                                     // idx 3
    scanA_kernel<<<NCHUNK, CHUNK, 0, g_s2>>>();                        // idx 4
    scanB_kernel<<<1, 128, 0, g_s2>>>();                               // idx 5
    scanC_kernel<<<NCHUNK, CHUNK, 0, g_s2>>>();                        // idx 6
    csr_fill_kernel<<<(NEDGES + 511) / 512, 512, 0, g_s2>>>(src, dst); // idx 7
    cudaEventRecord(g_ev_join, g_s2);

    // join: agg1 needs CSR + norms (s2) and gemm1 (main)
    cudaStreamWaitEvent(0, g_ev_join, 0);

    agg1_kernel<<<(NNODES * 32 + 255) / 256, 256>>>(b1);
    gemm2_kernel<<<(NNODES + 255) / 256, 256>>>(W2);
    agg2_kernel<<<(NNODES * 32 + 255) / 256, 256>>>(b2, out);
}

// round 6
// speedup vs baseline: 1.5948x; 1.4200x over previous
#include <cuda_runtime.h>
#include <cuda_bf16.h>
#include <math.h>
#include <stdint.h>

#define NNODES 50000
#define NEDGES 800000
#define SEQLEN 32
#define EMBD   128
#define INFEAT 256
#define NHID   256
#define NCLS   40

#define CHUNK   512
#define NCHUNK  98      // 98*512 = 50176 >= 50000

typedef unsigned long long ull;

// ---------------- scratch (device globals; no allocation allowed) ------------
__device__ int   g_deg_out[NNODES];
__device__ int   g_deg_in[NNODES];
__device__ float g_norm_s[NNODES];
__device__ float g_norm_d[NNODES];
__device__ int   g_row_ptr[NNODES + 1];
__device__ int   g_cursor[NNODES];
__device__ int   g_chunk_sum[NCHUNK];
__device__ int   g_chunk_off[NCHUNK];
__device__ int   g_csr_src[NEDGES];
__device__ float g_h[(size_t)NNODES * INFEAT];          // pooled embeddings fp32
__device__ __align__(16) uint32_t g_w1t[NHID * INFEAT]; // W1^T [n][k] tf32 bits
__device__ __align__(16) __nv_bfloat16 g_hw1b[(size_t)NNODES * NHID];   // h@W1 bf16
__device__ float g_out1[(size_t)NNODES * NHID];         // relu(agg*norm_d + b1)
__device__ float g_hws2[(size_t)NNODES * NCLS];         // (out1@W2)*norm_s

// ---------------- helpers -----------------------------------------------------
__device__ __forceinline__ ull ffma2(ull a, ull b, ull c) {
    ull d;
    asm("fma.rn.f32x2 %0, %1, %2, %3;" : "=l"(d) : "l"(a), "l"(b), "l"(c));
    return d;
}
__device__ __forceinline__ ull dup2(float x) {
    ull d;
    asm("mov.b64 %0, {%1, %1};" : "=l"(d) : "f"(x));
    return d;
}
__device__ __forceinline__ void unpack2(ull v, float& lo, float& hi) {
    asm("mov.b64 {%0, %1}, %2;" : "=f"(lo), "=f"(hi) : "l"(v));
}
__device__ __forceinline__ uint32_t f2tf32(float f) {
    uint32_t u;
    asm("cvt.rna.tf32.f32 %0, %1;" : "=r"(u) : "f"(f));
    return u;
}
__device__ __forceinline__ void mma_tf32(float* c, const uint32_t* a, uint32_t b0, uint32_t b1) {
    asm volatile(
        "mma.sync.aligned.m16n8k8.row.col.f32.tf32.tf32.f32 "
        "{%0,%1,%2,%3}, {%4,%5,%6,%7}, {%8,%9}, {%0,%1,%2,%3};"
        : "+f"(c[0]), "+f"(c[1]), "+f"(c[2]), "+f"(c[3])
        : "r"(a[0]), "r"(a[1]), "r"(a[2]), "r"(a[3]), "r"(b0), "r"(b1));
}

// ---------------- degree ------------------------------------------------------
__global__ void zero_degs_kernel() {
    int i = blockIdx.x * blockDim.x + threadIdx.x;
    if (i < NNODES) { g_deg_out[i] = 0; g_deg_in[i] = 0; }
}

__global__ void degree_kernel(const int* __restrict__ src, const int* __restrict__ dst) {
    int e = blockIdx.x * blockDim.x + threadIdx.x;
    if (e < NEDGES) {
        atomicAdd(&g_deg_out[src[e]], 1);
        atomicAdd(&g_deg_in[dst[e]], 1);
    }
}

// ---------------- scan + norms ------------------------------------------------
__global__ void scanA_kernel() {
    __shared__ int s[CHUNK];
    int t = threadIdx.x, b = blockIdx.x;
    int idx = b * CHUNK + t;
    int v = (idx < NNODES) ? g_deg_in[idx] : 0;
    s[t] = v;
    __syncthreads();
    for (int off = CHUNK / 2; off > 0; off >>= 1) {
        if (t < off) s[t] += s[t + off];
        __syncthreads();
    }
    if (t == 0) g_chunk_sum[b] = s[0];
}

__global__ void scanB_kernel() {
    __shared__ int s[128];
    int t = threadIdx.x;
    int v = (t < NCHUNK) ? g_chunk_sum[t] : 0;
    s[t] = v;
    __syncthreads();
    for (int off = 1; off < 128; off <<= 1) {
        int x = (t >= off) ? s[t - off] : 0;
        __syncthreads();
        s[t] += x;
        __syncthreads();
    }
    if (t < NCHUNK) g_chunk_off[t] = s[t] - v;
    if (t == 0) g_row_ptr[NNODES] = NEDGES;
}

__global__ void scanC_kernel() {
    __shared__ int s[CHUNK];
    int t = threadIdx.x, b = blockIdx.x;
    int idx = b * CHUNK + t;
    int v = (idx < NNODES) ? g_deg_in[idx] : 0;
    s[t] = v;
    __syncthreads();
    for (int off = 1; off < CHUNK; off <<= 1) {
        int x = (t >= off) ? s[t - off] : 0;
        __syncthreads();
        s[t] += x;
        __syncthreads();
    }
    if (idx < NNODES) {
        int excl = g_chunk_off[b] + s[t] - v;
        g_row_ptr[idx] = excl;
        g_cursor[idx]  = excl;
        int dins = v; if (dins < 1) dins = 1;
        int dofs = g_deg_out[idx]; if (dofs < 1) dofs = 1;
        g_norm_d[idx] = rsqrtf((float)dins);
        g_norm_s[idx] = rsqrtf((float)dofs);
    }
}

__global__ void csr_fill_kernel(const int* __restrict__ src, const int* __restrict__ dst) {
    int e = blockIdx.x * blockDim.x + threadIdx.x;
    if (e < NEDGES) {
        int d = dst[e];
        int pos = atomicAdd(&g_cursor[d], 1);
        g_csr_src[pos] = src[e];
    }
}

// ---------------- embedding pooling (warp per node, fp32 output) -------------
__global__ void embed_kernel(const int* __restrict__ feats, const float* __restrict__ emb) {
    int gt   = blockIdx.x * blockDim.x + threadIdx.x;
    int node = gt >> 5;
    int lane = gt & 31;
    if (node >= NNODES) return;

    int tok = feats[node * SEQLEN + lane];
    int cnt = __popc(__ballot_sync(0xffffffffu, tok != 0));
    if (cnt < 1) cnt = 1;

    float4 s  = make_float4(0.f, 0.f, 0.f, 0.f);
    float4 mx = make_float4(-INFINITY, -INFINITY, -INFINITY, -INFINITY);

#pragma unroll
    for (int t = 0; t < 32; t++) {
        int tk = __shfl_sync(0xffffffffu, tok, t);
        float4 v = make_float4(0.f, 0.f, 0.f, 0.f);
        if (tk != 0) v = *(const float4*)&emb[(size_t)tk * EMBD + lane * 4];
        s.x += v.x; s.y += v.y; s.z += v.z; s.w += v.w;
        mx.x = fmaxf(mx.x, v.x); mx.y = fmaxf(mx.y, v.y);
        mx.z = fmaxf(mx.z, v.z); mx.w = fmaxf(mx.w, v.w);
    }
    float inv = 1.0f / (float)cnt;
    float4 h1 = make_float4(s.x * inv, s.y * inv, s.z * inv, s.w * inv);
    size_t base = (size_t)node * INFEAT;
    *(float4*)&g_h[base + lane * 4]        = h1;
    *(float4*)&g_h[base + EMBD + lane * 4] = mx;
}

// ---------------- prep W1: [K][N] fp32 -> [N][K] tf32 bits -------------------
__global__ void prep_w1_kernel(const float* __restrict__ W1) {
    int i = blockIdx.x * blockDim.x + threadIdx.x;   // 65536
    int n = i >> 8, k = i & 255;
    g_w1t[n * INFEAT + k] = f2tf32(W1[k * NHID + n]);
}

// ---------------- GEMM1 via mma.sync tf32 ------------------------------------
// CTA 128x128, 8 warps (4m x 2n), warp tile 32x64, K chunks of 32, double buf.
#define KC 32
#define ASTR 36   // 32 + 4 pad words; (g*36 + tig) % 32 = (4g+tig) -> conflict-free

__global__ __launch_bounds__(256, 2)
void gemm1_mma_kernel() {
    extern __shared__ __align__(16) uint32_t smem[];
    uint32_t* As = smem;                    // [2][128][ASTR]
    uint32_t* Bs = smem + 2 * 128 * ASTR;   // [2][128][ASTR]

    int tid = threadIdx.x, wid = tid >> 5, lane = tid & 31;
    int wm = wid & 3, wn = wid >> 2;
    int g = lane >> 2, tig = lane & 3;
    int bm = blockIdx.x * 128, bn = blockIdx.y * 128;

    int lrow = tid >> 1, lhalf = (tid & 1) * 16;   // 2 threads/row, 16 floats each

    float acc[2][8][4];
#pragma unroll
    for (int mi = 0; mi < 2; mi++)
#pragma unroll
        for (int ni = 0; ni < 8; ni++)
#pragma unroll
            for (int q = 0; q < 4; q++) acc[mi][ni][q] = 0.f;

    float4 ar[4]; uint4 br[4];
    // preload chunk 0
    {
        int arow = bm + lrow;
#pragma unroll
        for (int q = 0; q < 4; q++) {
            ar[q] = make_float4(0.f, 0.f, 0.f, 0.f);
            if (arow < NNODES)
                ar[q] = *(const float4*)&g_h[(size_t)arow * INFEAT + lhalf + 4 * q];
            br[q] = *(const uint4*)&g_w1t[(bn + lrow) * INFEAT + lhalf + 4 * q];
        }
    }
#pragma unroll
    for (int q = 0; q < 4; q++) {
        uint32_t* a = &As[lrow * ASTR + lhalf + 4 * q];
        a[0] = f2tf32(ar[q].x); a[1] = f2tf32(ar[q].y);
        a[2] = f2tf32(ar[q].z); a[3] = f2tf32(ar[q].w);
        *(uint4*)&Bs[lrow * ASTR + lhalf + 4 * q] = br[q];
    }
    __syncthreads();

    const int NKC = INFEAT / KC;   // 8
    for (int kc = 0; kc < NKC; kc++) {
        int cur = kc & 1, nxt = cur ^ 1;
        if (kc + 1 < NKC) {
            int k0 = (kc + 1) * KC;
            int arow = bm + lrow;
#pragma unroll
            for (int q = 0; q < 4; q++) {
                ar[q] = make_float4(0.f, 0.f, 0.f, 0.f);
                if (arow < NNODES)
                    ar[q] = *(const float4*)&g_h[(size_t)arow * INFEAT + k0 + lhalf + 4 * q];
                br[q] = *(const uint4*)&g_w1t[(bn + lrow) * INFEAT + k0 + lhalf + 4 * q];
            }
        }

        const uint32_t* Ac = &As[cur * 128 * ASTR];
        const uint32_t* Bc = &Bs[cur * 128 * ASTR];
#pragma unroll
        for (int ks = 0; ks < 4; ks++) {
            int kb = ks * 8;
            uint32_t af[2][4];
#pragma unroll
            for (int mi = 0; mi < 2; mi++) {
                int r = wm * 32 + mi * 16 + g;
                af[mi][0] = Ac[r * ASTR + kb + tig];
                af[mi][1] = Ac[(r + 8) * ASTR + kb + tig];
                af[mi][2] = Ac[r * ASTR + kb + tig + 4];
                af[mi][3] = Ac[(r + 8) * ASTR + kb + tig + 4];
            }
#pragma unroll
            for (int ni = 0; ni < 8; ni++) {
                int nr = wn * 64 + ni * 8 + g;
                uint32_t b0 = Bc[nr * ASTR + kb + tig];
                uint32_t b1 = Bc[nr * ASTR + kb + tig + 4];
                mma_tf32(acc[0][ni], af[0], b0, b1);
                mma_tf32(acc[1][ni], af[1], b0, b1);
            }
        }

        if (kc + 1 < NKC) {
            __syncthreads();
#pragma unroll
            for (int q = 0; q < 4; q++) {
                uint32_t* a = &As[(nxt * 128 + lrow) * ASTR + lhalf + 4 * q];
                a[0] = f2tf32(ar[q].x); a[1] = f2tf32(ar[q].y);
                a[2] = f2tf32(ar[q].z); a[3] = f2tf32(ar[q].w);
                *(uint4*)&Bs[(nxt * 128 + lrow) * ASTR + lhalf + 4 * q] = br[q];
            }
            __syncthreads();
        }
    }

    // epilogue: bf16 store (c0,c1 -> row g, cols 2tig,2tig+1; c2,c3 -> row g+8)
#pragma unroll
    for (int mi = 0; mi < 2; mi++) {
        int r0 = bm + wm * 32 + mi * 16 + g;
        int r1 = r0 + 8;
#pragma unroll
        for (int ni = 0; ni < 8; ni++) {
            int col = bn + wn * 64 + ni * 8 + tig * 2;
            if (r0 < NNODES) {
                __nv_bfloat162 p = __float22bfloat162_rn(make_float2(acc[mi][ni][0], acc[mi][ni][1]));
                *(unsigned*)&g_hw1b[(size_t)r0 * NHID + col] = *(unsigned*)&p;
            }
            if (r1 < NNODES) {
                __nv_bfloat162 p = __float22bfloat162_rn(make_float2(acc[mi][ni][2], acc[mi][ni][3]));
                *(unsigned*)&g_hw1b[(size_t)r1 * NHID + col] = *(unsigned*)&p;
            }
        }
    }
}
#define G1_SMEM (4 * 128 * ASTR * 4)   // 73728 bytes

// ---------------- agg layer 1 (bf16 messages, warp per node) -----------------
__global__ void agg1_kernel(const float* __restrict__ b1) {
    int gt   = blockIdx.x * blockDim.x + threadIdx.x;
    int node = gt >> 5;
    int lane = gt & 31;
    if (node >= NNODES) return;

    int beg = g_row_ptr[node], end = g_row_ptr[node + 1];
    float acc[8] = {0.f, 0.f, 0.f, 0.f, 0.f, 0.f, 0.f, 0.f};

    int e = beg;
    for (; e + 1 < end; e += 2) {
        int s0 = g_csr_src[e], s1 = g_csr_src[e + 1];
        float n0 = g_norm_s[s0], n1 = g_norm_s[s1];
        uint4 u0 = *(const uint4*)&g_hw1b[(size_t)s0 * NHID + lane * 8];
        uint4 u1 = *(const uint4*)&g_hw1b[(size_t)s1 * NHID + lane * 8];
        const unsigned* w0 = &u0.x;
        const unsigned* w1 = &u1.x;
#pragma unroll
        for (int j = 0; j < 4; j++) {
            float2 f0 = __bfloat1622float2(*(const __nv_bfloat162*)&w0[j]);
            float2 f1 = __bfloat1622float2(*(const __nv_bfloat162*)&w1[j]);
            acc[2 * j]     += f0.x * n0 + f1.x * n1;
            acc[2 * j + 1] += f0.y * n0 + f1.y * n1;
        }
    }
    if (e < end) {
        int s0 = g_csr_src[e];
        float n0 = g_norm_s[s0];
        uint4 u0 = *(const uint4*)&g_hw1b[(size_t)s0 * NHID + lane * 8];
        const unsigned* w0 = &u0.x;
#pragma unroll
        for (int j = 0; j < 4; j++) {
            float2 f0 = __bfloat1622float2(*(const __nv_bfloat162*)&w0[j]);
            acc[2 * j]     += f0.x * n0;
            acc[2 * j + 1] += f0.y * n0;
        }
    }

    float nd = g_norm_d[node];
    float* dst = &g_out1[(size_t)node * NHID + lane * 8];
    float4 bb0 = *(const float4*)&b1[lane * 8];
    float4 bb1 = *(const float4*)&b1[lane * 8 + 4];
    float4 o0, o1;
    o0.x = fmaxf(acc[0] * nd + bb0.x, 0.f);
    o0.y = fmaxf(acc[1] * nd + bb0.y, 0.f);
    o0.z = fmaxf(acc[2] * nd + bb0.z, 0.f);
    o0.w = fmaxf(acc[3] * nd + bb0.w, 0.f);
    o1.x = fmaxf(acc[4] * nd + bb1.x, 0.f);
    o1.y = fmaxf(acc[5] * nd + bb1.y, 0.f);
    o1.z = fmaxf(acc[6] * nd + bb1.z, 0.f);
    o1.w = fmaxf(acc[7] * nd + bb1.w, 0.f);
    *(float4*)&dst[0] = o0;
    *(float4*)&dst[4] = o1;
}

// ---------------- GEMM2: hws2 = (out1 @ W2) * norm_s, f32x2 ------------------
__global__ __launch_bounds__(256)
void gemm2_kernel(const float* __restrict__ W2) {
    __shared__ __align__(16) float Ws[NHID * NCLS];
    for (int i = threadIdx.x; i < (NHID * NCLS) / 4; i += blockDim.x)
        ((float4*)Ws)[i] = ((const float4*)W2)[i];
    __syncthreads();

    int row = blockIdx.x * blockDim.x + threadIdx.x;
    if (row >= NNODES) return;

    ull acc[NCLS / 2];
#pragma unroll
    for (int c = 0; c < NCLS / 2; c++) acc[c] = 0ull;

    const float* a = &g_out1[(size_t)row * NHID];
    for (int k0 = 0; k0 < NHID; k0 += 4) {
        float4 av = *(const float4*)&a[k0];
        float a4[4] = {av.x, av.y, av.z, av.w};
#pragma unroll
        for (int kk = 0; kk < 4; kk++) {
            ull ad = dup2(a4[kk]);
            const ull* w = (const ull*)&Ws[(k0 + kk) * NCLS];
#pragma unroll
            for (int c = 0; c < NCLS / 2; c++) acc[c] = ffma2(ad, w[c], acc[c]);
        }
    }
    float ns = g_norm_s[row];
    float o[NCLS];
#pragma unroll
    for (int c = 0; c < NCLS / 2; c++) unpack2(acc[c], o[2 * c], o[2 * c + 1]);
    float* dst = &g_hws2[(size_t)row * NCLS];
#pragma unroll
    for (int c = 0; c < NCLS / 4; c++)
        ((float4*)dst)[c] = make_float4(o[4 * c] * ns, o[4 * c + 1] * ns,
                                        o[4 * c + 2] * ns, o[4 * c + 3] * ns);
}

// ---------------- agg layer 2 ------------------------------------------------
__global__ void agg2_kernel(const float* __restrict__ b2, float* __restrict__ out) {
    int gt   = blockIdx.x * blockDim.x + threadIdx.x;
    int node = gt >> 5;
    int lane = gt & 31;
    if (node >= NNODES) return;

    int beg = g_row_ptr[node], end = g_row_ptr[node + 1];
    float a0 = 0.f, a1 = 0.f;
    for (int e = beg; e < end; e++) {
        int s = g_csr_src[e];
        const float* r = &g_hws2[(size_t)s * NCLS];
        a0 += r[lane];
        if (lane < 8) a1 += r[32 + lane];
    }
    float nd = g_norm_d[node];
    out[(size_t)node * NCLS + lane] = a0 * nd + b2[lane];
    if (lane < 8)
        out[(size_t)node * NCLS + 32 + lane] = a1 * nd + b2[32 + lane];
}

// ---------------- launch ------------------------------------------------------
static cudaStream_t g_s2 = 0;
static cudaEvent_t  g_ev_fork = 0, g_ev_w1 = 0, g_ev_join = 0;

extern "C" void kernel_launch(void* const* d_in, const int* in_sizes, int n_in,
                              void* d_out, int out_size) {
    const int*   feats = (const int*)d_in[0];
    const int*   src   = (const int*)d_in[1];
    const int*   dst   = (const int*)d_in[2];
    const float* emb   = (const float*)d_in[3];
    const float* W1    = (const float*)d_in[4];
    const float* b1    = (const float*)d_in[5];
    const float* W2    = (const float*)d_in[6];
    const float* b2    = (const float*)d_in[7];
    float*       out   = (float*)d_out;

    if (!g_s2) {
        cudaStreamCreateWithFlags(&g_s2, cudaStreamNonBlocking);
        cudaEventCreateWithFlags(&g_ev_fork, cudaEventDisableTiming);
        cudaEventCreateWithFlags(&g_ev_w1, cudaEventDisableTiming);
        cudaEventCreateWithFlags(&g_ev_join, cudaEventDisableTiming);
        cudaFuncSetAttribute(gemm1_mma_kernel,
                             cudaFuncAttributeMaxDynamicSharedMemorySize, G1_SMEM);
    }

    // fork side stream
    cudaEventRecord(g_ev_fork, 0);
    cudaStreamWaitEvent(g_s2, g_ev_fork, 0);

    // main: embed; side: W1 prep + CSR chain
    embed_kernel<<<(NNODES * 32 + 255) / 256, 256>>>(feats, emb);
    prep_w1_kernel<<<256, 256, 0, g_s2>>>(W1);
    cudaEventRecord(g_ev_w1, g_s2);
    zero_degs_kernel<<<(NNODES + 511) / 512, 512, 0, g_s2>>>();
    degree_kernel<<<(NEDGES + 511) / 512, 512, 0, g_s2>>>(src, dst);
    scanA_kernel<<<NCHUNK, CHUNK, 0, g_s2>>>();
    scanB_kernel<<<1, 128, 0, g_s2>>>();
    scanC_kernel<<<NCHUNK, CHUNK, 0, g_s2>>>();
    csr_fill_kernel<<<(NEDGES + 511) / 512, 512, 0, g_s2>>>(src, dst);
    cudaEventRecord(g_ev_join, g_s2);

    // gemm1 needs embed (main) + W1 tf32 image (s2)
    cudaStreamWaitEvent(0, g_ev_w1, 0);
    dim3 g1((NNODES + 127) / 128, 1);
    gemm1_mma_kernel<<<dim3((NNODES + 127) / 128, 2), 256, G1_SMEM>>>();

    // agg1 needs CSR + norms
    cudaStreamWaitEvent(0, g_ev_join, 0);
    agg1_kernel<<<(NNODES * 32 + 255) / 256, 256>>>(b1);
    gemm2_kernel<<<(NNODES + 255) / 256, 256>>>(W2);
    agg2_kernel<<<(NNODES * 32 + 255) / 256, 256>>>(b2, out);
}